// round 10
// baseline (speedup 1.0000x reference)
#include <cuda_runtime.h>
#include <cuda_fp16.h>
#include <cstddef>

// Problem constants
#define NN   50000
#define EE   800000
#define FF   512
#define HH   128
#define CC   40
#define TOTE (EE + NN)          // edges + self loops
#define SCAN_BS 512
#define SCAN_NB ((NN + SCAN_BS - 1) / SCAN_BS)   // 98

// ---- packed f32x2 helpers (Blackwell FFMA2) ---------------------------------
#define UNPK2(lo, hi, s) asm("mov.b64 {%0, %1}, %2;" : "=f"(lo), "=f"(hi) : "l"(s))
#define FMA2(d, a, b) asm("fma.rn.f32x2 %0, %1, %2, %0;" : "+l"(d) : "l"(a), "l"(b))

// ---------------- static scratch (device globals; no allocation) -------------
__device__ float g_deg[NN];
__device__ float g_dinv[NN];
__device__ int   g_cnt[NN];
__device__ int   g_rowptr[NN + 1];
__device__ int   g_bsum[SCAN_NB];
__device__ int   g_boff[SCAN_NB];
__device__ int   g_csrc[TOTE];
__device__ float g_cnorm[TOTE];

__device__ float  g_cc[(size_t)NN * 640];   // [h | Sh | S2h | S3h | S4h]
__device__ __half g_h16a[(size_t)NN * HH];  // fp16 ping
__device__ __half g_h16b[(size_t)NN * HH];  // fp16 pong
__device__ float g_r[NN];
__device__ float g_sr[NN];
__device__ float g_s2r[NN];

__device__ float g_Acat[5 * HH * CC];      // 5 blocks of 128x40
__device__ float g_uc[CC];
__device__ float g_ur_p[3 * CC];           // contributions from branches 2,3,4
__device__ float g_usr_p[2 * CC];          // from branches 3,4
__device__ float g_us2r[CC];               // from branch 4

// ---------------- graph preprocessing ---------------------------------------

__global__ void k_init() {
    int i = blockIdx.x * blockDim.x + threadIdx.x;
    if (i < NN) { g_deg[i] = 1.0f; g_cnt[i] = 1; }   // self loop
}

__global__ void k_deg(const int* __restrict__ dst, const float* __restrict__ ew) {
    int e = blockIdx.x * blockDim.x + threadIdx.x;
    if (e < EE) {
        int d = dst[e];
        atomicAdd(&g_deg[d], ew[e]);
        atomicAdd(&g_cnt[d], 1);
    }
}

__global__ void k_scan1() {
    __shared__ int sh[SCAN_BS];
    int t = threadIdx.x;
    int idx = blockIdx.x * SCAN_BS + t;
    int v = (idx < NN) ? g_cnt[idx] : 0;
    sh[t] = v;
    __syncthreads();
    for (int off = 1; off < SCAN_BS; off <<= 1) {
        int x = (t >= off) ? sh[t - off] : 0;
        __syncthreads();
        sh[t] += x;
        __syncthreads();
    }
    if (idx < NN) g_rowptr[idx] = sh[t] - v;
    if (t == SCAN_BS - 1) g_bsum[blockIdx.x] = sh[t];
}

__global__ void k_scan2() {
    __shared__ int sh[128];
    int t = threadIdx.x;
    int v = (t < SCAN_NB) ? g_bsum[t] : 0;
    sh[t] = v;
    __syncthreads();
    for (int off = 1; off < 128; off <<= 1) {
        int x = (t >= off) ? sh[t - off] : 0;
        __syncthreads();
        sh[t] += x;
        __syncthreads();
    }
    if (t < SCAN_NB) g_boff[t] = sh[t] - v;   // exclusive
}

__global__ void k_scan3() {
    int t = threadIdx.x;
    int idx = blockIdx.x * SCAN_BS + t;
    if (idx < NN) g_rowptr[idx] += g_boff[blockIdx.x];
    if (idx == 0) g_rowptr[NN] = TOTE;
}

__global__ void k_dinv_self() {
    int n = blockIdx.x * blockDim.x + threadIdx.x;
    if (n < NN) {
        float di = rsqrtf(g_deg[n]);
        g_dinv[n] = di;
        int p = g_rowptr[n];
        g_csrc[p]  = n;
        g_cnorm[p] = di * di;
        g_cnt[n]   = 1;
    }
}

__global__ void k_fill(const int* __restrict__ src, const int* __restrict__ dst,
                       const float* __restrict__ ew) {
    int e = blockIdx.x * blockDim.x + threadIdx.x;
    if (e < EE) {
        int s = src[e], d = dst[e];
        int off = atomicAdd(&g_cnt[d], 1);
        int p = g_rowptr[d] + off;
        g_csrc[p]  = s;
        g_cnorm[p] = g_dinv[s] * ew[e] * g_dinv[d];
    }
}

// r-chain: vout[n] = sum_row cnorm * vin[src]   (vin==nullptr -> vin==1)
__global__ void __launch_bounds__(256) k_spmv_vec(const float* __restrict__ vin,
                                                  float* __restrict__ vout) {
    int w = (blockIdx.x * blockDim.x + threadIdx.x) >> 5;
    int lane = threadIdx.x & 31;
    if (w >= NN) return;
    int beg = g_rowptr[w], end = g_rowptr[w + 1];
    float a = 0.f;
    for (int i = beg + lane; i < end; i += 32)
        a += g_cnorm[i] * (vin ? vin[g_csrc[i]] : 1.0f);
    for (int o = 16; o; o >>= 1) a += __shfl_down_sync(0xffffffffu, a, o);
    if (lane == 0) vout[w] = a;
}

// ---------------- dense GEMM: C[M,128] = A[M,K] @ B[K,128] + bias ------------
// Tile 128x128, 256 threads, 8x8 micro-tile, pack-free FFMA2 mainloop.
// A smem tile stored duplicated ([2r]=[2r+1]=a_r) so LDS.128 gives (a,a) pairs.
// Also emits fp16 mirror of C when h16 != nullptr.
template<int K>
__global__ void __launch_bounds__(256) gemm_t128(
    const float* __restrict__ A, const float* __restrict__ B,
    const float* __restrict__ bias,
    float* __restrict__ C, int ldc, __half* __restrict__ h16, int M)
{
    __shared__ float  As[16][260];     // duplicated: col 2r,2r+1 = a_r
    __shared__ float4 Bs4[16 * 32];

    const int t = threadIdx.x;
    const int ty = t >> 4;        // 0..15 -> 8 rows (ty*8 ..)
    const int tx = t & 15;        // 0..15 -> 8 cols (tx*8 ..)
    const int ar  = t >> 2;       // 0..63
    const int seg = t & 3;        // 0..3
    const int rowbase = blockIdx.x * 128;

    unsigned long long acc[8][4];
#pragma unroll
    for (int i = 0; i < 8; i++)
#pragma unroll
        for (int j = 0; j < 4; j++) acc[i][j] = 0ull;

    for (int kc = 0; kc < K; kc += 16) {
        // A tile: transpose + duplicate
#pragma unroll
        for (int rep = 0; rep < 2; rep++) {
            int r = ar + rep * 64;
            int row = rowbase + r;
            float4 av = make_float4(0.f, 0.f, 0.f, 0.f);
            if (row < M) av = *(const float4*)(A + (size_t)row * K + kc + seg * 4);
            *(float2*)&As[seg * 4 + 0][2 * r] = make_float2(av.x, av.x);
            *(float2*)&As[seg * 4 + 1][2 * r] = make_float2(av.y, av.y);
            *(float2*)&As[seg * 4 + 2][2 * r] = make_float2(av.z, av.z);
            *(float2*)&As[seg * 4 + 3][2 * r] = make_float2(av.w, av.w);
        }
        // B tile
#pragma unroll
        for (int rep = 0; rep < 2; rep++) {
            int idx = t + rep * 256;
            int k = idx >> 5, c = idx & 31;
            Bs4[idx] = *(const float4*)(B + (size_t)(kc + k) * 128 + c * 4);
        }
        __syncthreads();

#pragma unroll
        for (int k = 0; k < 16; k++) {
            ulonglong2 bp = *(const ulonglong2*)&Bs4[k * 32 + tx * 2];       // cols 8tx..+3
            ulonglong2 bq = *(const ulonglong2*)&Bs4[k * 32 + tx * 2 + 1];   // cols 8tx+4..+7
#pragma unroll
            for (int jj = 0; jj < 4; jj++) {
                ulonglong2 ap = *(const ulonglong2*)&As[k][ty * 16 + 4 * jj];
                const int r0 = 2 * jj, r1 = 2 * jj + 1;
                FMA2(acc[r0][0], ap.x, bp.x);
                FMA2(acc[r0][1], ap.x, bp.y);
                FMA2(acc[r0][2], ap.x, bq.x);
                FMA2(acc[r0][3], ap.x, bq.y);
                FMA2(acc[r1][0], ap.y, bp.x);
                FMA2(acc[r1][1], ap.y, bp.y);
                FMA2(acc[r1][2], ap.y, bq.x);
                FMA2(acc[r1][3], ap.y, bq.y);
            }
        }
        __syncthreads();
    }

    float4 bb0 = ((const float4*)bias)[tx * 2];
    float4 bb1 = ((const float4*)bias)[tx * 2 + 1];
#pragma unroll
    for (int i = 0; i < 8; i++) {
        int row = rowbase + ty * 8 + i;
        if (row < M) {
            float4 r0, r1;
            UNPK2(r0.x, r0.y, acc[i][0]);
            UNPK2(r0.z, r0.w, acc[i][1]);
            UNPK2(r1.x, r1.y, acc[i][2]);
            UNPK2(r1.z, r1.w, acc[i][3]);
            r0.x += bb0.x; r0.y += bb0.y; r0.z += bb0.z; r0.w += bb0.w;
            r1.x += bb1.x; r1.y += bb1.y; r1.z += bb1.z; r1.w += bb1.w;
            float4* cp = (float4*)(C + (size_t)row * ldc);
            cp[tx * 2]     = r0;
            cp[tx * 2 + 1] = r1;
            if (h16) {
                __half2 o0 = __floats2half2_rn(r0.x, r0.y);
                __half2 o1 = __floats2half2_rn(r0.z, r0.w);
                __half2 o2 = __floats2half2_rn(r1.x, r1.y);
                __half2 o3 = __floats2half2_rn(r1.z, r1.w);
                uint4 o;
                o.x = *(unsigned*)&o0; o.y = *(unsigned*)&o1;
                o.z = *(unsigned*)&o2; o.w = *(unsigned*)&o3;
                *(uint4*)(h16 + (size_t)row * HH + tx * 8) = o;
            }
        }
    }
}

// ---------------- sparse aggregation (fp16 gather) ---------------------------
// out_cc[n] (fp32, stride 640) = sum norm * in16[src]; also fp16 copy if out16.
// One warp per node; lane handles 4 features (one uint2 = 4 halfs).
__global__ void __launch_bounds__(256) agg16(
    const __half* __restrict__ in16, float* __restrict__ out_cc,
    __half* __restrict__ out16)
{
    int w = (blockIdx.x * blockDim.x + threadIdx.x) >> 5;
    int lane = threadIdx.x & 31;
    if (w >= NN) return;

    int beg = g_rowptr[w];
    int end = g_rowptr[w + 1];
    const uint2* in4 = (const uint2*)in16;   // 4 halfs per uint2; 32 per row

    float4 acc = make_float4(0.f, 0.f, 0.f, 0.f);
    int i = beg;
    for (; i + 1 < end; i += 2) {
        int s0 = g_csrc[i], s1 = g_csrc[i + 1];
        float w0 = g_cnorm[i], w1 = g_cnorm[i + 1];
        uint2 u0 = in4[(size_t)s0 * 32 + lane];
        uint2 u1 = in4[(size_t)s1 * 32 + lane];
        float2 a0 = __half22float2(*(__half2*)&u0.x);
        float2 a1 = __half22float2(*(__half2*)&u0.y);
        float2 b0 = __half22float2(*(__half2*)&u1.x);
        float2 b1 = __half22float2(*(__half2*)&u1.y);
        acc.x += w0 * a0.x + w1 * b0.x;
        acc.y += w0 * a0.y + w1 * b0.y;
        acc.z += w0 * a1.x + w1 * b1.x;
        acc.w += w0 * a1.y + w1 * b1.y;
    }
    if (i < end) {
        int s = g_csrc[i];
        float wt = g_cnorm[i];
        uint2 u = in4[(size_t)s * 32 + lane];
        float2 a0 = __half22float2(*(__half2*)&u.x);
        float2 a1 = __half22float2(*(__half2*)&u.y);
        acc.x += wt * a0.x; acc.y += wt * a0.y;
        acc.z += wt * a1.x; acc.w += wt * a1.y;
    }
    *(float4*)(out_cc + (size_t)w * 640 + lane * 4) = acc;
    if (out16) {
        __half2 o0 = __floats2half2_rn(acc.x, acc.y);
        __half2 o1 = __floats2half2_rn(acc.z, acc.w);
        uint2 o;
        o.x = *(unsigned*)&o0; o.y = *(unsigned*)&o1;
        ((uint2*)out16)[(size_t)w * 32 + lane] = o;
    }
}

// ---------------- right-to-left weight chains --------------------------------
__global__ void __launch_bounds__(256) k_chains(
    const float* __restrict__ W_gcn, const float* __restrict__ b_gcn,
    const float* __restrict__ W_out, const float* __restrict__ b_out)
{
    __shared__ float tA[HH * CC];
    __shared__ float tB[HH * CC];
    const int b = blockIdx.x;
    const int t = threadIdx.x;

    if (b == 0) {
        for (int i = t; i < HH * CC; i += 256) g_Acat[i] = W_out[i];
        if (t < CC) {
            float s = b_out[t];
            for (int k = 0; k < HH; k++) {
                s += b_gcn[0 * HH + k] * W_out[(size_t)(1 * HH + k) * CC + t];
                s += b_gcn[2 * HH + k] * W_out[(size_t)(2 * HH + k) * CC + t];
                s += b_gcn[5 * HH + k] * W_out[(size_t)(3 * HH + k) * CC + t];
                s += b_gcn[9 * HH + k] * W_out[(size_t)(4 * HH + k) * CC + t];
            }
            g_uc[t] = s;
        }
        return;
    }

    for (int i = t; i < HH * CC; i += 256) tA[i] = W_out[(size_t)b * HH * CC + i];
    __syncthreads();

    float* cur = tA;
    float* nxt = tB;
    const int start = (b - 1) * b / 2;

    const int row = t >> 1;     // 0..127
    const int half = t & 1;     // 0..1 -> 20 cols each

    for (int p = 1; p <= b; p++) {
        const float* Wr = W_gcn + (size_t)(start + b - p) * HH * HH + (size_t)row * HH;
        float acc[20];
#pragma unroll
        for (int c = 0; c < 20; c++) acc[c] = 0.f;
        for (int k = 0; k < HH; k++) {
            float a = Wr[k];
            const float* srcp = cur + k * CC + half * 20;
#pragma unroll
            for (int c = 0; c < 20; c++) acc[c] += a * srcp[c];
        }
        float* dstp = nxt + row * CC + half * 20;
#pragma unroll
        for (int c = 0; c < 20; c++) dstp[c] = acc[c];
        __syncthreads();

        if (p < b && t < CC) {
            const float* bb = b_gcn + (size_t)(start + b - p - 1) * HH;
            float s = 0.f;
            for (int k = 0; k < HH; k++) s += bb[k] * nxt[k * CC + t];
            if (p == 1)      g_ur_p[(b - 2) * CC + t] = s;
            else if (p == 2) g_usr_p[(b - 3) * CC + t] = s;
            else             g_us2r[t] = s;
        }
        float* tmp = cur; cur = nxt; nxt = tmp;
    }

    for (int i = t; i < HH * CC; i += 256)
        g_Acat[(size_t)b * HH * CC + i] = cur[i];
}

// ---------------- partial output GEMM: C (+)= q[M,128] @ Aj[128,40] ----------
template<bool INIT>
__global__ void __launch_bounds__(256) k_pout(
    const float* __restrict__ q, const float* __restrict__ Aj,
    float* __restrict__ C, int M)
{
    __shared__ float Bsf[HH * CC];
    __shared__ float As[16][129];
    __shared__ float su_c[CC], su_r[CC], su_sr[CC], su_s2r[CC];

    const int t = threadIdx.x;
    for (int i = t; i < HH * CC; i += 256) Bsf[i] = Aj[i];
    if (INIT && t < CC) {
        su_c[t]   = g_uc[t];
        su_r[t]   = g_ur_p[t] + g_ur_p[CC + t] + g_ur_p[2 * CC + t];
        su_sr[t]  = g_usr_p[t] + g_usr_p[CC + t];
        su_s2r[t] = g_us2r[t];
    }

    const int rg = t >> 3;   // 0..31
    const int cg = t & 7;    // 0..7
    const int rowbase = blockIdx.x * 128;

    float acc[4][5];
#pragma unroll
    for (int i = 0; i < 4; i++)
#pragma unroll
        for (int j = 0; j < 5; j++) acc[i][j] = 0.f;

    for (int kc = 0; kc < HH; kc += 16) {
#pragma unroll
        for (int rep = 0; rep < 2; rep++) {
            int idx = t + rep * 256;
            int r = idx >> 2, seg = idx & 3;
            int row = rowbase + r;
            float4 av = make_float4(0.f, 0.f, 0.f, 0.f);
            if (row < M) av = *(const float4*)(q + (size_t)row * 640 + kc + seg * 4);
            As[seg * 4 + 0][r] = av.x;
            As[seg * 4 + 1][r] = av.y;
            As[seg * 4 + 2][r] = av.z;
            As[seg * 4 + 3][r] = av.w;
        }
        __syncthreads();

#pragma unroll
        for (int k = 0; k < 16; k++) {
            float a0 = As[k][rg], a1 = As[k][rg + 32], a2 = As[k][rg + 64], a3 = As[k][rg + 96];
#pragma unroll
            for (int j = 0; j < 5; j++) {
                float bv = Bsf[(kc + k) * CC + cg + 8 * j];
                acc[0][j] += a0 * bv; acc[1][j] += a1 * bv;
                acc[2][j] += a2 * bv; acc[3][j] += a3 * bv;
            }
        }
        __syncthreads();
    }

#pragma unroll
    for (int i = 0; i < 4; i++) {
        int row = rowbase + rg + 32 * i;
        if (row < M) {
            if (INIT) {
                float rv = g_r[row], srv = g_sr[row], s2rv = g_s2r[row];
#pragma unroll
                for (int j = 0; j < 5; j++) {
                    int col = cg + 8 * j;
                    C[(size_t)row * CC + col] = acc[i][j] + su_c[col]
                        + rv * su_r[col] + srv * su_sr[col] + s2rv * su_s2r[col];
                }
            } else {
#pragma unroll
                for (int j = 0; j < 5; j++) {
                    int col = cg + 8 * j;
                    C[(size_t)row * CC + col] += acc[i][j];
                }
            }
        }
    }
}

// ---------------- stream/event setup at static-init (outside checkpoints) ----
struct StreamInit {
    bool ok = false;
    int dev = -1;
    cudaStream_t sB{}, sC{};
    cudaEvent_t ev[12]{};
    StreamInit() {
        ok = (cudaStreamCreateWithFlags(&sB, cudaStreamNonBlocking) == cudaSuccess) &&
             (cudaStreamCreateWithFlags(&sC, cudaStreamNonBlocking) == cudaSuccess);
        for (int i = 0; i < 12 && ok; i++)
            ok = (cudaEventCreateWithFlags(&ev[i], cudaEventDisableTiming) == cudaSuccess);
        if (ok) cudaGetDevice(&dev);
    }
};
static StreamInit g_si;

// ---------------- host driver ------------------------------------------------

extern "C" void kernel_launch(void* const* d_in, const int* in_sizes, int n_in,
                              void* d_out, int out_size)
{
    (void)in_sizes; (void)n_in; (void)out_size;

    const float* x     = (const float*)d_in[0];
    const int*   ei    = (const int*)d_in[1];
    const float* ew    = (const float*)d_in[2];
    const float* W_in  = (const float*)d_in[3];
    const float* b_in  = (const float*)d_in[4];
    const float* W_gcn = (const float*)d_in[5];  // [10,128,128]
    const float* b_gcn = (const float*)d_in[6];  // [10,128]
    const float* W_out = (const float*)d_in[7];  // [640,40]
    const float* b_out = (const float*)d_in[8];
    float* outp = (float*)d_out;

    const int* src = ei;
    const int* dst = ei + EE;

    float *p_cc, *p_r, *p_sr, *p_s2r, *p_acat;
    __half *p_h16a, *p_h16b;
    cudaGetSymbolAddress((void**)&p_cc,   g_cc);
    cudaGetSymbolAddress((void**)&p_r,    g_r);
    cudaGetSymbolAddress((void**)&p_sr,   g_sr);
    cudaGetSymbolAddress((void**)&p_s2r,  g_s2r);
    cudaGetSymbolAddress((void**)&p_acat, g_Acat);
    cudaGetSymbolAddress((void**)&p_h16a, g_h16a);
    cudaGetSymbolAddress((void**)&p_h16b, g_h16b);

    int curdev = -1;
    cudaGetDevice(&curdev);
    const bool par = g_si.ok && (curdev == g_si.dev);
    cudaStream_t s0 = 0;
    cudaStream_t sB = par ? g_si.sB : (cudaStream_t)0;
    cudaStream_t sC = par ? g_si.sC : (cudaStream_t)0;
    cudaEvent_t e0   = g_si.ev[0], eB = g_si.ev[1], eW = g_si.ev[2];
    cudaEvent_t eCSR = g_si.ev[3], eR = g_si.ev[4];
    cudaEvent_t eA0  = g_si.ev[5], eA1 = g_si.ev[6], eA2 = g_si.ev[7], eA3 = g_si.ev[8];
    cudaEvent_t eF   = g_si.ev[9];

    // fork
    if (par) {
        cudaEventRecord(e0, s0);
        cudaStreamWaitEvent(sB, e0, 0);
        cudaStreamWaitEvent(sC, e0, 0);
    }

    // sB: input linear h = x @ W_in + b_in -> cc block 0 (+ fp16 mirror)
    const int GT = (NN + 127) / 128;
    gemm_t128<FF><<<GT, 256, 0, sB>>>(x, W_in, b_in, p_cc, 640, p_h16a, NN);
    if (par) cudaEventRecord(eB, sB);

    // sC: weight chains (Acat + bias folds), then r-chain after CSR
    k_chains<<<5, 256, 0, sC>>>(W_gcn, b_gcn, W_out, b_out);
    if (par) cudaEventRecord(eW, sC);

    // s0: CSR build
    k_init<<<(NN + 255) / 256, 256, 0, s0>>>();
    k_deg<<<(EE + 255) / 256, 256, 0, s0>>>(dst, ew);
    k_scan1<<<SCAN_NB, SCAN_BS, 0, s0>>>();
    k_scan2<<<1, 128, 0, s0>>>();
    k_scan3<<<SCAN_NB, SCAN_BS, 0, s0>>>();
    k_dinv_self<<<(NN + 255) / 256, 256, 0, s0>>>();
    k_fill<<<(EE + 255) / 256, 256, 0, s0>>>(src, dst, ew);
    if (par) cudaEventRecord(eCSR, s0);

    // sC: r chain (after CSR)
    const int VEC_GRID = (NN * 32 + 255) / 256;
    if (par) cudaStreamWaitEvent(sC, eCSR, 0);
    k_spmv_vec<<<VEC_GRID, 256, 0, sC>>>(nullptr, p_r);
    k_spmv_vec<<<VEC_GRID, 256, 0, sC>>>(p_r, p_sr);
    k_spmv_vec<<<VEC_GRID, 256, 0, sC>>>(p_sr, p_s2r);
    if (par) cudaEventRecord(eR, sC);

    // s0: fp16 aggregation chain (CSR ordered on s0; needs h16 from sB)
    if (par) cudaStreamWaitEvent(s0, eB, 0);
    agg16<<<VEC_GRID, 256, 0, s0>>>(p_h16a, p_cc + 1 * HH, p_h16b);
    if (par) cudaEventRecord(eA0, s0);
    agg16<<<VEC_GRID, 256, 0, s0>>>(p_h16b, p_cc + 2 * HH, p_h16a);
    if (par) cudaEventRecord(eA1, s0);
    agg16<<<VEC_GRID, 256, 0, s0>>>(p_h16a, p_cc + 3 * HH, p_h16b);
    if (par) cudaEventRecord(eA2, s0);
    agg16<<<VEC_GRID, 256, 0, s0>>>(p_h16b, p_cc + 4 * HH, nullptr);
    if (par) cudaEventRecord(eA3, s0);

    // sB: partial output GEMMs as each q block completes
    const int PG = (NN + 127) / 128;
    if (par) { cudaStreamWaitEvent(sB, eW, 0); cudaStreamWaitEvent(sB, eR, 0); }
    k_pout<true><<<PG, 256, 0, sB>>>(p_cc + 0 * HH, p_acat + 0 * HH * CC, outp, NN);
    if (par) cudaStreamWaitEvent(sB, eA0, 0);
    k_pout<false><<<PG, 256, 0, sB>>>(p_cc + 1 * HH, p_acat + 1 * HH * CC, outp, NN);
    if (par) cudaStreamWaitEvent(sB, eA1, 0);
    k_pout<false><<<PG, 256, 0, sB>>>(p_cc + 2 * HH, p_acat + 2 * HH * CC, outp, NN);
    if (par) cudaStreamWaitEvent(sB, eA2, 0);
    k_pout<false><<<PG, 256, 0, sB>>>(p_cc + 3 * HH, p_acat + 3 * HH * CC, outp, NN);
    if (par) cudaStreamWaitEvent(sB, eA3, 0);
    k_pout<false><<<PG, 256, 0, sB>>>(p_cc + 4 * HH, p_acat + 4 * HH * CC, outp, NN);

    // join back to capture stream
    if (par) {
        cudaEventRecord(eF, sB);
        cudaStreamWaitEvent(s0, eF, 0);
    }
}

// round 14
// speedup vs baseline: 1.2040x; 1.2040x over previous
#include <cuda_runtime.h>
#include <cuda_fp16.h>
#include <cstddef>

// Problem constants
#define NN   50000
#define EE   800000
#define FF   512
#define HH   128
#define CC   40
#define TOTE (EE + NN)          // edges + self loops
#define SCAN_BS 512
#define SCAN_NB ((NN + SCAN_BS - 1) / SCAN_BS)   // 98

// ---------------- static scratch (device globals; no allocation) -------------
__device__ float g_deg[NN];
__device__ float g_dinv[NN];
__device__ int   g_cnt[NN];
__device__ int   g_rowptr[NN + 1];
__device__ int   g_bsum[SCAN_NB];
__device__ int   g_boff[SCAN_NB];
__device__ int   g_csrc[TOTE];
__device__ float g_cnorm[TOTE];

__device__ float  g_cc[(size_t)NN * 640];   // [h | Sh | S2h | S3h | S4h]
__device__ __half g_h16a[(size_t)NN * HH];  // fp16 ping
__device__ __half g_h16b[(size_t)NN * HH];  // fp16 pong
__device__ float g_r[NN];
__device__ float g_sr[NN];
__device__ float g_s2r[NN];

__device__ float g_Acat[5 * HH * CC];      // 5 blocks of 128x40
__device__ float g_uc[CC];
__device__ float g_ur_p[3 * CC];           // contributions from branches 2,3,4
__device__ float g_usr_p[2 * CC];          // from branches 3,4
__device__ float g_us2r[CC];               // from branch 4

// ---------------- graph preprocessing ---------------------------------------

__global__ void k_init() {
    int i = blockIdx.x * blockDim.x + threadIdx.x;
    if (i < NN) { g_deg[i] = 1.0f; g_cnt[i] = 1; }   // self loop
}

__global__ void k_deg(const int* __restrict__ dst, const float* __restrict__ ew) {
    int e = blockIdx.x * blockDim.x + threadIdx.x;
    if (e < EE) {
        int d = dst[e];
        atomicAdd(&g_deg[d], ew[e]);
        atomicAdd(&g_cnt[d], 1);
    }
}

__global__ void k_scan1() {
    __shared__ int sh[SCAN_BS];
    int t = threadIdx.x;
    int idx = blockIdx.x * SCAN_BS + t;
    int v = (idx < NN) ? g_cnt[idx] : 0;
    sh[t] = v;
    __syncthreads();
    for (int off = 1; off < SCAN_BS; off <<= 1) {
        int x = (t >= off) ? sh[t - off] : 0;
        __syncthreads();
        sh[t] += x;
        __syncthreads();
    }
    if (idx < NN) g_rowptr[idx] = sh[t] - v;
    if (t == SCAN_BS - 1) g_bsum[blockIdx.x] = sh[t];
}

__global__ void k_scan2() {
    __shared__ int sh[128];
    int t = threadIdx.x;
    int v = (t < SCAN_NB) ? g_bsum[t] : 0;
    sh[t] = v;
    __syncthreads();
    for (int off = 1; off < 128; off <<= 1) {
        int x = (t >= off) ? sh[t - off] : 0;
        __syncthreads();
        sh[t] += x;
        __syncthreads();
    }
    if (t < SCAN_NB) g_boff[t] = sh[t] - v;   // exclusive
}

__global__ void k_scan3() {
    int t = threadIdx.x;
    int idx = blockIdx.x * SCAN_BS + t;
    if (idx < NN) g_rowptr[idx] += g_boff[blockIdx.x];
    if (idx == 0) g_rowptr[NN] = TOTE;
}

__global__ void k_dinv_self() {
    int n = blockIdx.x * blockDim.x + threadIdx.x;
    if (n < NN) {
        float di = rsqrtf(g_deg[n]);
        g_dinv[n] = di;
        int p = g_rowptr[n];
        g_csrc[p]  = n;
        g_cnorm[p] = di * di;
        g_cnt[n]   = 1;
    }
}

__global__ void k_fill(const int* __restrict__ src, const int* __restrict__ dst,
                       const float* __restrict__ ew) {
    int e = blockIdx.x * blockDim.x + threadIdx.x;
    if (e < EE) {
        int s = src[e], d = dst[e];
        int off = atomicAdd(&g_cnt[d], 1);
        int p = g_rowptr[d] + off;
        g_csrc[p]  = s;
        g_cnorm[p] = g_dinv[s] * ew[e] * g_dinv[d];
    }
}

// r-chain: vout[n] = sum_row cnorm * vin[src]   (vin==nullptr -> vin==1)
__global__ void __launch_bounds__(256) k_spmv_vec(const float* __restrict__ vin,
                                                  float* __restrict__ vout) {
    int w = (blockIdx.x * blockDim.x + threadIdx.x) >> 5;
    int lane = threadIdx.x & 31;
    if (w >= NN) return;
    int beg = g_rowptr[w], end = g_rowptr[w + 1];
    float a = 0.f;
    for (int i = beg + lane; i < end; i += 32)
        a += g_cnorm[i] * (vin ? vin[g_csrc[i]] : 1.0f);
    for (int o = 16; o; o >>= 1) a += __shfl_down_sync(0xffffffffu, a, o);
    if (lane == 0) vout[w] = a;
}

// ---------------- dense GEMM: C[M,128] = A[M,K] @ B[K,128] (+bias) -----------
// tile 128x128, 256 threads, 8x8 micro-tile (scalar fp32 — proven fastest).
// Optionally emits fp16 mirror of C (dense layout, stride HH).
template<int K>
__global__ void __launch_bounds__(256) gemm_t128(
    const float* __restrict__ A, const float* __restrict__ B,
    const float* __restrict__ bias,
    float* __restrict__ C, int ldc, __half* __restrict__ h16, int M)
{
    __shared__ float  As[16][129];
    __shared__ float4 Bs4[16 * 32];

    const int t = threadIdx.x;
    const int ty = t >> 4;        // 0..15
    const int tx = t & 15;        // 0..15
    const int rowbase = blockIdx.x * 128;

    float4 acc[8][2];
#pragma unroll
    for (int i = 0; i < 8; i++) {
        acc[i][0] = make_float4(0.f, 0.f, 0.f, 0.f);
        acc[i][1] = make_float4(0.f, 0.f, 0.f, 0.f);
    }

    const int lr  = t >> 2;       // 0..63
    const int seg = t & 3;        // 0..3

    for (int kc = 0; kc < K; kc += 16) {
#pragma unroll
        for (int rep = 0; rep < 2; rep++) {
            int r = lr + rep * 64;
            int row = rowbase + r;
            float4 av = make_float4(0.f, 0.f, 0.f, 0.f);
            if (row < M) av = *(const float4*)(A + (size_t)row * K + kc + seg * 4);
            As[seg * 4 + 0][r] = av.x;
            As[seg * 4 + 1][r] = av.y;
            As[seg * 4 + 2][r] = av.z;
            As[seg * 4 + 3][r] = av.w;
        }
#pragma unroll
        for (int rep = 0; rep < 2; rep++) {
            int idx = t + rep * 256;
            int k = idx >> 5, c = idx & 31;
            Bs4[idx] = *(const float4*)(B + (size_t)(kc + k) * 128 + c * 4);
        }
        __syncthreads();

#pragma unroll
        for (int k = 0; k < 16; k++) {
            float4 b0 = Bs4[k * 32 + tx * 2];
            float4 b1 = Bs4[k * 32 + tx * 2 + 1];
#pragma unroll
            for (int i = 0; i < 8; i++) {
                float a = As[k][ty * 8 + i];
                acc[i][0].x += a * b0.x; acc[i][0].y += a * b0.y;
                acc[i][0].z += a * b0.z; acc[i][0].w += a * b0.w;
                acc[i][1].x += a * b1.x; acc[i][1].y += a * b1.y;
                acc[i][1].z += a * b1.z; acc[i][1].w += a * b1.w;
            }
        }
        __syncthreads();
    }

    float4 bb0 = make_float4(0.f, 0.f, 0.f, 0.f);
    float4 bb1 = make_float4(0.f, 0.f, 0.f, 0.f);
    if (bias) {
        bb0 = ((const float4*)bias)[tx * 2];
        bb1 = ((const float4*)bias)[tx * 2 + 1];
    }
#pragma unroll
    for (int i = 0; i < 8; i++) {
        int row = rowbase + ty * 8 + i;
        if (row < M) {
            float4 r0 = acc[i][0], r1 = acc[i][1];
            r0.x += bb0.x; r0.y += bb0.y; r0.z += bb0.z; r0.w += bb0.w;
            r1.x += bb1.x; r1.y += bb1.y; r1.z += bb1.z; r1.w += bb1.w;
            float4* cp = (float4*)(C + (size_t)row * ldc);
            cp[tx * 2]     = r0;
            cp[tx * 2 + 1] = r1;
            if (h16) {
                __half2 o0 = __floats2half2_rn(r0.x, r0.y);
                __half2 o1 = __floats2half2_rn(r0.z, r0.w);
                __half2 o2 = __floats2half2_rn(r1.x, r1.y);
                __half2 o3 = __floats2half2_rn(r1.z, r1.w);
                uint4 o;
                o.x = *(unsigned*)&o0; o.y = *(unsigned*)&o1;
                o.z = *(unsigned*)&o2; o.w = *(unsigned*)&o3;
                *(uint4*)(h16 + (size_t)row * HH + tx * 8) = o;
            }
        }
    }
}

// ---------------- sparse aggregation (fp16 gather) ---------------------------
// out_cc[n] (fp32, stride 640) = sum norm * in16[src]; fp16 copy if out16.
// One warp per node; lane handles 4 features (uint2 = 4 halfs).
__global__ void __launch_bounds__(256) agg16(
    const __half* __restrict__ in16, float* __restrict__ out_cc,
    __half* __restrict__ out16)
{
    int w = (blockIdx.x * blockDim.x + threadIdx.x) >> 5;
    int lane = threadIdx.x & 31;
    if (w >= NN) return;

    int beg = g_rowptr[w];
    int end = g_rowptr[w + 1];
    const uint2* in4 = (const uint2*)in16;   // 4 halfs per uint2; 32 per row

    float4 acc = make_float4(0.f, 0.f, 0.f, 0.f);
    int i = beg;
    for (; i + 1 < end; i += 2) {
        int s0 = g_csrc[i], s1 = g_csrc[i + 1];
        float w0 = g_cnorm[i], w1 = g_cnorm[i + 1];
        uint2 u0 = in4[(size_t)s0 * 32 + lane];
        uint2 u1 = in4[(size_t)s1 * 32 + lane];
        float2 a0 = __half22float2(*(__half2*)&u0.x);
        float2 a1 = __half22float2(*(__half2*)&u0.y);
        float2 b0 = __half22float2(*(__half2*)&u1.x);
        float2 b1 = __half22float2(*(__half2*)&u1.y);
        acc.x += w0 * a0.x + w1 * b0.x;
        acc.y += w0 * a0.y + w1 * b0.y;
        acc.z += w0 * a1.x + w1 * b1.x;
        acc.w += w0 * a1.y + w1 * b1.y;
    }
    if (i < end) {
        int s = g_csrc[i];
        float wt = g_cnorm[i];
        uint2 u = in4[(size_t)s * 32 + lane];
        float2 a0 = __half22float2(*(__half2*)&u.x);
        float2 a1 = __half22float2(*(__half2*)&u.y);
        acc.x += wt * a0.x; acc.y += wt * a0.y;
        acc.z += wt * a1.x; acc.w += wt * a1.y;
    }
    *(float4*)(out_cc + (size_t)w * 640 + lane * 4) = acc;
    if (out16) {
        __half2 o0 = __floats2half2_rn(acc.x, acc.y);
        __half2 o1 = __floats2half2_rn(acc.z, acc.w);
        uint2 o;
        o.x = *(unsigned*)&o0; o.y = *(unsigned*)&o1;
        ((uint2*)out16)[(size_t)w * 32 + lane] = o;
    }
}

// ---------------- right-to-left weight chains --------------------------------
__global__ void __launch_bounds__(256) k_chains(
    const float* __restrict__ W_gcn, const float* __restrict__ b_gcn,
    const float* __restrict__ W_out, const float* __restrict__ b_out)
{
    __shared__ float tA[HH * CC];
    __shared__ float tB[HH * CC];
    const int b = blockIdx.x;
    const int t = threadIdx.x;

    if (b == 0) {
        for (int i = t; i < HH * CC; i += 256) g_Acat[i] = W_out[i];
        if (t < CC) {
            float s = b_out[t];
            for (int k = 0; k < HH; k++) {
                s += b_gcn[0 * HH + k] * W_out[(size_t)(1 * HH + k) * CC + t];
                s += b_gcn[2 * HH + k] * W_out[(size_t)(2 * HH + k) * CC + t];
                s += b_gcn[5 * HH + k] * W_out[(size_t)(3 * HH + k) * CC + t];
                s += b_gcn[9 * HH + k] * W_out[(size_t)(4 * HH + k) * CC + t];
            }
            g_uc[t] = s;
        }
        return;
    }

    for (int i = t; i < HH * CC; i += 256) tA[i] = W_out[(size_t)b * HH * CC + i];
    __syncthreads();

    float* cur = tA;
    float* nxt = tB;
    const int start = (b - 1) * b / 2;

    const int row = t >> 1;     // 0..127
    const int half = t & 1;     // 0..1 -> 20 cols each

    for (int p = 1; p <= b; p++) {
        const float* Wr = W_gcn + (size_t)(start + b - p) * HH * HH + (size_t)row * HH;
        float acc[20];
#pragma unroll
        for (int c = 0; c < 20; c++) acc[c] = 0.f;
        for (int k = 0; k < HH; k++) {
            float a = Wr[k];
            const float* srcp = cur + k * CC + half * 20;
#pragma unroll
            for (int c = 0; c < 20; c++) acc[c] += a * srcp[c];
        }
        float* dstp = nxt + row * CC + half * 20;
#pragma unroll
        for (int c = 0; c < 20; c++) dstp[c] = acc[c];
        __syncthreads();

        if (p < b && t < CC) {
            const float* bb = b_gcn + (size_t)(start + b - p - 1) * HH;
            float s = 0.f;
            for (int k = 0; k < HH; k++) s += bb[k] * nxt[k * CC + t];
            if (p == 1)      g_ur_p[(b - 2) * CC + t] = s;
            else if (p == 2) g_usr_p[(b - 3) * CC + t] = s;
            else             g_us2r[t] = s;
        }
        float* tmp = cur; cur = nxt; nxt = tmp;
    }

    for (int i = t; i < HH * CC; i += 256)
        g_Acat[(size_t)b * HH * CC + i] = cur[i];
}

// ---------------- partial output GEMM: C (+)= q[M,128] @ Aj[128,40] ----------
template<bool INIT>
__global__ void __launch_bounds__(256) k_pout(
    const float* __restrict__ q, const float* __restrict__ Aj,
    float* __restrict__ C, int M)
{
    __shared__ float Bsf[HH * CC];
    __shared__ float As[16][129];
    __shared__ float su_c[CC], su_r[CC], su_sr[CC], su_s2r[CC];

    const int t = threadIdx.x;
    for (int i = t; i < HH * CC; i += 256) Bsf[i] = Aj[i];
    if (INIT && t < CC) {
        su_c[t]   = g_uc[t];
        su_r[t]   = g_ur_p[t] + g_ur_p[CC + t] + g_ur_p[2 * CC + t];
        su_sr[t]  = g_usr_p[t] + g_usr_p[CC + t];
        su_s2r[t] = g_us2r[t];
    }

    const int rg = t >> 3;   // 0..31
    const int cg = t & 7;    // 0..7
    const int rowbase = blockIdx.x * 128;

    float acc[4][5];
#pragma unroll
    for (int i = 0; i < 4; i++)
#pragma unroll
        for (int j = 0; j < 5; j++) acc[i][j] = 0.f;

    for (int kc = 0; kc < HH; kc += 16) {
#pragma unroll
        for (int rep = 0; rep < 2; rep++) {
            int idx = t + rep * 256;
            int r = idx >> 2, seg = idx & 3;
            int row = rowbase + r;
            float4 av = make_float4(0.f, 0.f, 0.f, 0.f);
            if (row < M) av = *(const float4*)(q + (size_t)row * 640 + kc + seg * 4);
            As[seg * 4 + 0][r] = av.x;
            As[seg * 4 + 1][r] = av.y;
            As[seg * 4 + 2][r] = av.z;
            As[seg * 4 + 3][r] = av.w;
        }
        __syncthreads();

#pragma unroll
        for (int k = 0; k < 16; k++) {
            float a0 = As[k][rg], a1 = As[k][rg + 32], a2 = As[k][rg + 64], a3 = As[k][rg + 96];
#pragma unroll
            for (int j = 0; j < 5; j++) {
                float bv = Bsf[(kc + k) * CC + cg + 8 * j];
                acc[0][j] += a0 * bv; acc[1][j] += a1 * bv;
                acc[2][j] += a2 * bv; acc[3][j] += a3 * bv;
            }
        }
        __syncthreads();
    }

#pragma unroll
    for (int i = 0; i < 4; i++) {
        int row = rowbase + rg + 32 * i;
        if (row < M) {
            if (INIT) {
                float rv = g_r[row], srv = g_sr[row], s2rv = g_s2r[row];
#pragma unroll
                for (int j = 0; j < 5; j++) {
                    int col = cg + 8 * j;
                    C[(size_t)row * CC + col] = acc[i][j] + su_c[col]
                        + rv * su_r[col] + srv * su_sr[col] + s2rv * su_s2r[col];
                }
            } else {
#pragma unroll
                for (int j = 0; j < 5; j++) {
                    int col = cg + 8 * j;
                    C[(size_t)row * CC + col] += acc[i][j];
                }
            }
        }
    }
}

// ---------------- stream/event setup at static-init (outside checkpoints) ----
struct StreamInit {
    bool ok = false;
    int dev = -1;
    cudaStream_t sB{}, sC{};
    cudaEvent_t ev[10]{};
    StreamInit() {
        ok = (cudaStreamCreateWithFlags(&sB, cudaStreamNonBlocking) == cudaSuccess) &&
             (cudaStreamCreateWithFlags(&sC, cudaStreamNonBlocking) == cudaSuccess);
        for (int i = 0; i < 10 && ok; i++)
            ok = (cudaEventCreateWithFlags(&ev[i], cudaEventDisableTiming) == cudaSuccess);
        if (ok) cudaGetDevice(&dev);
    }
};
static StreamInit g_si;

// ---------------- host driver ------------------------------------------------

extern "C" void kernel_launch(void* const* d_in, const int* in_sizes, int n_in,
                              void* d_out, int out_size)
{
    (void)in_sizes; (void)n_in; (void)out_size;

    const float* x     = (const float*)d_in[0];
    const int*   ei    = (const int*)d_in[1];
    const float* ew    = (const float*)d_in[2];
    const float* W_in  = (const float*)d_in[3];
    const float* b_in  = (const float*)d_in[4];
    const float* W_gcn = (const float*)d_in[5];  // [10,128,128]
    const float* b_gcn = (const float*)d_in[6];  // [10,128]
    const float* W_out = (const float*)d_in[7];  // [640,40]
    const float* b_out = (const float*)d_in[8];
    float* outp = (float*)d_out;

    const int* src = ei;
    const int* dst = ei + EE;

    float *p_cc, *p_r, *p_sr, *p_s2r, *p_acat;
    __half *p_h16a, *p_h16b;
    cudaGetSymbolAddress((void**)&p_cc,   g_cc);
    cudaGetSymbolAddress((void**)&p_r,    g_r);
    cudaGetSymbolAddress((void**)&p_sr,   g_sr);
    cudaGetSymbolAddress((void**)&p_s2r,  g_s2r);
    cudaGetSymbolAddress((void**)&p_acat, g_Acat);
    cudaGetSymbolAddress((void**)&p_h16a, g_h16a);
    cudaGetSymbolAddress((void**)&p_h16b, g_h16b);

    int curdev = -1;
    cudaGetDevice(&curdev);
    const bool par = g_si.ok && (curdev == g_si.dev);
    cudaStream_t s0 = 0;
    cudaStream_t sB = par ? g_si.sB : (cudaStream_t)0;
    cudaStream_t sC = par ? g_si.sC : (cudaStream_t)0;
    cudaEvent_t e0   = g_si.ev[0], eB = g_si.ev[1], eC = g_si.ev[2], eR = g_si.ev[3];
    cudaEvent_t eA0  = g_si.ev[4], eA1 = g_si.ev[5], eA2 = g_si.ev[6], eA3 = g_si.ev[7];
    cudaEvent_t eF   = g_si.ev[8];

    // fork
    if (par) {
        cudaEventRecord(e0, s0);
        cudaStreamWaitEvent(sB, e0, 0);
        cudaStreamWaitEvent(sC, e0, 0);
    }

    // sB: input linear h = x @ W_in + b_in -> cc block 0 (+ fp16 mirror)
    const int GT = (NN + 127) / 128;
    gemm_t128<FF><<<GT, 256, 0, sB>>>(x, W_in, b_in, p_cc, 640, p_h16a, NN);
    if (par) cudaEventRecord(eB, sB);

    // sC: weight chains (Acat + bias folds)
    k_chains<<<5, 256, 0, sC>>>(W_gcn, b_gcn, W_out, b_out);
    if (par) cudaEventRecord(eC, sC);

    // s0: CSR build
    k_init<<<(NN + 255) / 256, 256, 0, s0>>>();
    k_deg<<<(EE + 255) / 256, 256, 0, s0>>>(dst, ew);
    k_scan1<<<SCAN_NB, SCAN_BS, 0, s0>>>();
    k_scan2<<<1, 128, 0, s0>>>();
    k_scan3<<<SCAN_NB, SCAN_BS, 0, s0>>>();
    k_dinv_self<<<(NN + 255) / 256, 256, 0, s0>>>();
    k_fill<<<(EE + 255) / 256, 256, 0, s0>>>(src, dst, ew);

    // s0: r chain
    const int VEC_GRID = (NN * 32 + 255) / 256;
    k_spmv_vec<<<VEC_GRID, 256, 0, s0>>>(nullptr, p_r);
    k_spmv_vec<<<VEC_GRID, 256, 0, s0>>>(p_r, p_sr);
    k_spmv_vec<<<VEC_GRID, 256, 0, s0>>>(p_sr, p_s2r);
    if (par) cudaEventRecord(eR, s0);

    // s0: fp16 aggregation chain (needs h16 from sB)
    if (par) cudaStreamWaitEvent(s0, eB, 0);
    agg16<<<VEC_GRID, 256, 0, s0>>>(p_h16a, p_cc + 1 * HH, p_h16b);
    if (par) cudaEventRecord(eA0, s0);
    agg16<<<VEC_GRID, 256, 0, s0>>>(p_h16b, p_cc + 2 * HH, p_h16a);
    if (par) cudaEventRecord(eA1, s0);
    agg16<<<VEC_GRID, 256, 0, s0>>>(p_h16a, p_cc + 3 * HH, p_h16b);
    if (par) cudaEventRecord(eA2, s0);
    agg16<<<VEC_GRID, 256, 0, s0>>>(p_h16b, p_cc + 4 * HH, nullptr);
    if (par) cudaEventRecord(eA3, s0);

    // sB: partial output GEMMs, each as its q block becomes ready
    const int PG = (NN + 127) / 128;
    if (par) { cudaStreamWaitEvent(sB, eC, 0); cudaStreamWaitEvent(sB, eR, 0); }
    k_pout<true><<<PG, 256, 0, sB>>>(p_cc + 0 * HH, p_acat + 0 * HH * CC, outp, NN);
    if (par) cudaStreamWaitEvent(sB, eA0, 0);
    k_pout<false><<<PG, 256, 0, sB>>>(p_cc + 1 * HH, p_acat + 1 * HH * CC, outp, NN);
    if (par) cudaStreamWaitEvent(sB, eA1, 0);
    k_pout<false><<<PG, 256, 0, sB>>>(p_cc + 2 * HH, p_acat + 2 * HH * CC, outp, NN);
    if (par) cudaStreamWaitEvent(sB, eA2, 0);
    k_pout<false><<<PG, 256, 0, sB>>>(p_cc + 3 * HH, p_acat + 3 * HH * CC, outp, NN);
    if (par) cudaStreamWaitEvent(sB, eA3, 0);
    k_pout<false><<<PG, 256, 0, sB>>>(p_cc + 4 * HH, p_acat + 4 * HH * CC, outp, NN);

    // join back to capture stream
    if (par) {
        cudaEventRecord(eF, sB);
        cudaStreamWaitEvent(s0, eF, 0);
    }
}

// round 17
// speedup vs baseline: 1.2560x; 1.0432x over previous
#include <cuda_runtime.h>
#include <cuda_fp16.h>
#include <cuda_bf16.h>
#include <cstdint>
#include <cstddef>

// Problem constants
#define NN   50000
#define EE   800000
#define FF   512
#define HH   128
#define CC   40
#define TOTE (EE + NN)          // edges + self loops
#define SCAN_BS 512
#define SCAN_NB ((NN + SCAN_BS - 1) / SCAN_BS)   // 98

// ---------------- static scratch (device globals; no allocation) -------------
__device__ float g_deg[NN];
__device__ float g_dinv[NN];
__device__ int   g_cnt[NN];
__device__ int   g_rowptr[NN + 1];
__device__ int   g_bsum[SCAN_NB];
__device__ int   g_boff[SCAN_NB];
__device__ int   g_csrc[TOTE];
__device__ float g_cnorm[TOTE];

__device__ float  g_cc[(size_t)NN * 640];   // [h | Sh | S2h | S3h | S4h]
__device__ __half g_h16a[(size_t)NN * HH];  // fp16 ping
__device__ __half g_h16b[(size_t)NN * HH];  // fp16 pong
__device__ float g_r[NN];
__device__ float g_sr[NN];
__device__ float g_s2r[NN];

__device__ float g_Acat[5 * HH * CC];      // 5 blocks of 128x40
__device__ float g_uc[CC];
__device__ float g_ur_p[3 * CC];
__device__ float g_usr_p[2 * CC];
__device__ float g_us2r[CC];

// ---------------- graph preprocessing ---------------------------------------

__global__ void k_init() {
    int i = blockIdx.x * blockDim.x + threadIdx.x;
    if (i < NN) { g_deg[i] = 1.0f; g_cnt[i] = 1; }
}

__global__ void k_deg(const int* __restrict__ dst, const float* __restrict__ ew) {
    int e = blockIdx.x * blockDim.x + threadIdx.x;
    if (e < EE) {
        int d = dst[e];
        atomicAdd(&g_deg[d], ew[e]);
        atomicAdd(&g_cnt[d], 1);
    }
}

__global__ void k_scan1() {
    __shared__ int sh[SCAN_BS];
    int t = threadIdx.x;
    int idx = blockIdx.x * SCAN_BS + t;
    int v = (idx < NN) ? g_cnt[idx] : 0;
    sh[t] = v;
    __syncthreads();
    for (int off = 1; off < SCAN_BS; off <<= 1) {
        int x = (t >= off) ? sh[t - off] : 0;
        __syncthreads();
        sh[t] += x;
        __syncthreads();
    }
    if (idx < NN) g_rowptr[idx] = sh[t] - v;
    if (t == SCAN_BS - 1) g_bsum[blockIdx.x] = sh[t];
}

__global__ void k_scan2() {
    __shared__ int sh[128];
    int t = threadIdx.x;
    int v = (t < SCAN_NB) ? g_bsum[t] : 0;
    sh[t] = v;
    __syncthreads();
    for (int off = 1; off < 128; off <<= 1) {
        int x = (t >= off) ? sh[t - off] : 0;
        __syncthreads();
        sh[t] += x;
        __syncthreads();
    }
    if (t < SCAN_NB) g_boff[t] = sh[t] - v;
}

__global__ void k_scan3() {
    int t = threadIdx.x;
    int idx = blockIdx.x * SCAN_BS + t;
    if (idx < NN) g_rowptr[idx] += g_boff[blockIdx.x];
    if (idx == 0) g_rowptr[NN] = TOTE;
}

__global__ void k_dinv_self() {
    int n = blockIdx.x * blockDim.x + threadIdx.x;
    if (n < NN) {
        float di = rsqrtf(g_deg[n]);
        g_dinv[n] = di;
        int p = g_rowptr[n];
        g_csrc[p]  = n;
        g_cnorm[p] = di * di;
        g_cnt[n]   = 1;
    }
}

__global__ void k_fill(const int* __restrict__ src, const int* __restrict__ dst,
                       const float* __restrict__ ew) {
    int e = blockIdx.x * blockDim.x + threadIdx.x;
    if (e < EE) {
        int s = src[e], d = dst[e];
        int off = atomicAdd(&g_cnt[d], 1);
        int p = g_rowptr[d] + off;
        g_csrc[p]  = s;
        g_cnorm[p] = g_dinv[s] * ew[e] * g_dinv[d];
    }
}

__global__ void __launch_bounds__(256) k_spmv_vec(const float* __restrict__ vin,
                                                  float* __restrict__ vout) {
    int w = (blockIdx.x * blockDim.x + threadIdx.x) >> 5;
    int lane = threadIdx.x & 31;
    if (w >= NN) return;
    int beg = g_rowptr[w], end = g_rowptr[w + 1];
    float a = 0.f;
    for (int i = beg + lane; i < end; i += 32)
        a += g_cnorm[i] * (vin ? vin[g_csrc[i]] : 1.0f);
    for (int o = 16; o; o >>= 1) a += __shfl_down_sync(0xffffffffu, a, o);
    if (lane == 0) vout[w] = a;
}

// ---------------- HMMA input GEMM (mma.sync bf16 hi/lo split) ----------------
// C[M,128] = x[M,512] @ W[512,128] + bias, 3-term bf16 split, fp32 accum.
// Emits fp32 (stride 640) + fp16 mirror (stride 128).
// 128x128 tile / CTA, 256 threads (8 warps), warp = 16-row strip x 128 cols.

#define MMA16816(c, a0, a1, a2, a3, b0, b1) \
    asm volatile("mma.sync.aligned.m16n8k16.row.col.f32.bf16.bf16.f32 " \
        "{%0,%1,%2,%3}, {%4,%5,%6,%7}, {%8,%9}, {%0,%1,%2,%3};" \
        : "+f"((c)[0]), "+f"((c)[1]), "+f"((c)[2]), "+f"((c)[3]) \
        : "r"(a0), "r"(a1), "r"(a2), "r"(a3), "r"(b0), "r"(b1))

__global__ void __launch_bounds__(256) gemm_mma_in(
    const float* __restrict__ A, const float* __restrict__ W,
    const float* __restrict__ bias,
    float* __restrict__ C, __half* __restrict__ h16)
{
    __shared__ __nv_bfloat16 sAh[128][16];   // [row][k]
    __shared__ __nv_bfloat16 sAl[128][16];
    __shared__ __nv_bfloat16 sBh[128][16];   // [n][k]  (transposed W)
    __shared__ __nv_bfloat16 sBl[128][16];
    __shared__ float sBias[HH];

    const int tid  = threadIdx.x;
    const int wid  = tid >> 5;
    const int lane = tid & 31;
    const int g    = lane >> 2;   // 0..7
    const int tig  = lane & 3;    // 0..3
    const int rowbase = blockIdx.x * 128;

    if (tid < HH) sBias[tid] = bias[tid];

    float acc[16][4];
#pragma unroll
    for (int i = 0; i < 16; i++)
#pragma unroll
        for (int j = 0; j < 4; j++) acc[i][j] = 0.f;

    for (int ch = 0; ch < 32; ch++) {
        const int kc = ch * 16;

        // A tile: 128 rows x 16 k, fp32 -> bf16 hi/lo
#pragma unroll
        for (int i = 0; i < 2; i++) {
            int idx = tid + i * 256;       // 0..511
            int r = idx >> 2, c4 = idx & 3;
            int row = rowbase + r;
            float4 v = make_float4(0.f, 0.f, 0.f, 0.f);
            if (row < NN) v = *(const float4*)(A + (size_t)row * FF + kc + c4 * 4);
            __nv_bfloat16 h0 = __float2bfloat16_rn(v.x);
            __nv_bfloat16 h1 = __float2bfloat16_rn(v.y);
            __nv_bfloat16 h2 = __float2bfloat16_rn(v.z);
            __nv_bfloat16 h3 = __float2bfloat16_rn(v.w);
            __nv_bfloat16 l0 = __float2bfloat16_rn(v.x - __bfloat162float(h0));
            __nv_bfloat16 l1 = __float2bfloat16_rn(v.y - __bfloat162float(h1));
            __nv_bfloat16 l2 = __float2bfloat16_rn(v.z - __bfloat162float(h2));
            __nv_bfloat16 l3 = __float2bfloat16_rn(v.w - __bfloat162float(h3));
            __nv_bfloat162 hp0, hp1, lp0, lp1;
            hp0.x = h0; hp0.y = h1; hp1.x = h2; hp1.y = h3;
            lp0.x = l0; lp0.y = l1; lp1.x = l2; lp1.y = l3;
            uint2 hu, lu;
            hu.x = *(unsigned*)&hp0; hu.y = *(unsigned*)&hp1;
            lu.x = *(unsigned*)&lp0; lu.y = *(unsigned*)&lp1;
            *(uint2*)&sAh[r][c4 * 4] = hu;
            *(uint2*)&sAl[r][c4 * 4] = lu;
        }

        // B tile transposed: sB[n][k] = W[kc+k][n], hi/lo
#pragma unroll
        for (int i = 0; i < 2; i++) {
            int idx = tid + i * 256;       // 0..511
            int n = idx >> 2, k4 = idx & 3;
            float vv[4];
#pragma unroll
            for (int j = 0; j < 4; j++)
                vv[j] = W[(size_t)(kc + k4 * 4 + j) * HH + n];
            __nv_bfloat16 h0 = __float2bfloat16_rn(vv[0]);
            __nv_bfloat16 h1 = __float2bfloat16_rn(vv[1]);
            __nv_bfloat16 h2 = __float2bfloat16_rn(vv[2]);
            __nv_bfloat16 h3 = __float2bfloat16_rn(vv[3]);
            __nv_bfloat16 l0 = __float2bfloat16_rn(vv[0] - __bfloat162float(h0));
            __nv_bfloat16 l1 = __float2bfloat16_rn(vv[1] - __bfloat162float(h1));
            __nv_bfloat16 l2 = __float2bfloat16_rn(vv[2] - __bfloat162float(h2));
            __nv_bfloat16 l3 = __float2bfloat16_rn(vv[3] - __bfloat162float(h3));
            __nv_bfloat162 hp0, hp1, lp0, lp1;
            hp0.x = h0; hp0.y = h1; hp1.x = h2; hp1.y = h3;
            lp0.x = l0; lp0.y = l1; lp1.x = l2; lp1.y = l3;
            uint2 hu, lu;
            hu.x = *(unsigned*)&hp0; hu.y = *(unsigned*)&hp1;
            lu.x = *(unsigned*)&lp0; lu.y = *(unsigned*)&lp1;
            *(uint2*)&sBh[n][k4 * 4] = hu;
            *(uint2*)&sBl[n][k4 * 4] = lu;
        }
        __syncthreads();

        // A fragments (m16n8k16 lane mapping, row-major A)
        const int ar = wid * 16 + g;
        uint32_t ah0 = *(const uint32_t*)&sAh[ar][tig * 2];
        uint32_t ah1 = *(const uint32_t*)&sAh[ar + 8][tig * 2];
        uint32_t ah2 = *(const uint32_t*)&sAh[ar][tig * 2 + 8];
        uint32_t ah3 = *(const uint32_t*)&sAh[ar + 8][tig * 2 + 8];
        uint32_t al0 = *(const uint32_t*)&sAl[ar][tig * 2];
        uint32_t al1 = *(const uint32_t*)&sAl[ar + 8][tig * 2];
        uint32_t al2 = *(const uint32_t*)&sAl[ar][tig * 2 + 8];
        uint32_t al3 = *(const uint32_t*)&sAl[ar + 8][tig * 2 + 8];

#pragma unroll
        for (int nt = 0; nt < 16; nt++) {
            int bn = nt * 8 + g;
            uint32_t bh0 = *(const uint32_t*)&sBh[bn][tig * 2];
            uint32_t bh1 = *(const uint32_t*)&sBh[bn][tig * 2 + 8];
            uint32_t bl0 = *(const uint32_t*)&sBl[bn][tig * 2];
            uint32_t bl1 = *(const uint32_t*)&sBl[bn][tig * 2 + 8];
            MMA16816(acc[nt], ah0, ah1, ah2, ah3, bh0, bh1);
            MMA16816(acc[nt], al0, al1, al2, al3, bh0, bh1);
            MMA16816(acc[nt], ah0, ah1, ah2, ah3, bl0, bl1);
        }
        __syncthreads();
    }

    // Epilogue: C fragment mapping -> fp32 cc + fp16 mirror
    const int r0 = rowbase + wid * 16 + g;
    const int r1 = r0 + 8;
#pragma unroll
    for (int nt = 0; nt < 16; nt++) {
        int col = nt * 8 + tig * 2;
        float b0 = sBias[col], b1 = sBias[col + 1];
        if (r0 < NN) {
            float2 v; v.x = acc[nt][0] + b0; v.y = acc[nt][1] + b1;
            *(float2*)(C + (size_t)r0 * 640 + col) = v;
            __half2 hh = __floats2half2_rn(v.x, v.y);
            *(__half2*)(h16 + (size_t)r0 * HH + col) = hh;
        }
        if (r1 < NN) {
            float2 v; v.x = acc[nt][2] + b0; v.y = acc[nt][3] + b1;
            *(float2*)(C + (size_t)r1 * 640 + col) = v;
            __half2 hh = __floats2half2_rn(v.x, v.y);
            *(__half2*)(h16 + (size_t)r1 * HH + col) = hh;
        }
    }
}

// ---------------- sparse aggregation (fp16 gather) ---------------------------
__global__ void __launch_bounds__(256) agg16(
    const __half* __restrict__ in16, float* __restrict__ out_cc,
    __half* __restrict__ out16)
{
    int w = (blockIdx.x * blockDim.x + threadIdx.x) >> 5;
    int lane = threadIdx.x & 31;
    if (w >= NN) return;

    int beg = g_rowptr[w];
    int end = g_rowptr[w + 1];
    const uint2* in4 = (const uint2*)in16;

    float4 acc = make_float4(0.f, 0.f, 0.f, 0.f);
    int i = beg;
    for (; i + 1 < end; i += 2) {
        int s0 = g_csrc[i], s1 = g_csrc[i + 1];
        float w0 = g_cnorm[i], w1 = g_cnorm[i + 1];
        uint2 u0 = in4[(size_t)s0 * 32 + lane];
        uint2 u1 = in4[(size_t)s1 * 32 + lane];
        float2 a0 = __half22float2(*(__half2*)&u0.x);
        float2 a1 = __half22float2(*(__half2*)&u0.y);
        float2 b0 = __half22float2(*(__half2*)&u1.x);
        float2 b1 = __half22float2(*(__half2*)&u1.y);
        acc.x += w0 * a0.x + w1 * b0.x;
        acc.y += w0 * a0.y + w1 * b0.y;
        acc.z += w0 * a1.x + w1 * b1.x;
        acc.w += w0 * a1.y + w1 * b1.y;
    }
    if (i < end) {
        int s = g_csrc[i];
        float wt = g_cnorm[i];
        uint2 u = in4[(size_t)s * 32 + lane];
        float2 a0 = __half22float2(*(__half2*)&u.x);
        float2 a1 = __half22float2(*(__half2*)&u.y);
        acc.x += wt * a0.x; acc.y += wt * a0.y;
        acc.z += wt * a1.x; acc.w += wt * a1.y;
    }
    *(float4*)(out_cc + (size_t)w * 640 + lane * 4) = acc;
    if (out16) {
        __half2 o0 = __floats2half2_rn(acc.x, acc.y);
        __half2 o1 = __floats2half2_rn(acc.z, acc.w);
        uint2 o;
        o.x = *(unsigned*)&o0; o.y = *(unsigned*)&o1;
        ((uint2*)out16)[(size_t)w * 32 + lane] = o;
    }
}

// ---------------- right-to-left weight chains --------------------------------
__global__ void __launch_bounds__(256) k_chains(
    const float* __restrict__ W_gcn, const float* __restrict__ b_gcn,
    const float* __restrict__ W_out, const float* __restrict__ b_out)
{
    __shared__ float tA[HH * CC];
    __shared__ float tB[HH * CC];
    const int b = blockIdx.x;
    const int t = threadIdx.x;

    if (b == 0) {
        for (int i = t; i < HH * CC; i += 256) g_Acat[i] = W_out[i];
        if (t < CC) {
            float s = b_out[t];
            for (int k = 0; k < HH; k++) {
                s += b_gcn[0 * HH + k] * W_out[(size_t)(1 * HH + k) * CC + t];
                s += b_gcn[2 * HH + k] * W_out[(size_t)(2 * HH + k) * CC + t];
                s += b_gcn[5 * HH + k] * W_out[(size_t)(3 * HH + k) * CC + t];
                s += b_gcn[9 * HH + k] * W_out[(size_t)(4 * HH + k) * CC + t];
            }
            g_uc[t] = s;
        }
        return;
    }

    for (int i = t; i < HH * CC; i += 256) tA[i] = W_out[(size_t)b * HH * CC + i];
    __syncthreads();

    float* cur = tA;
    float* nxt = tB;
    const int start = (b - 1) * b / 2;

    const int row = t >> 1;
    const int half = t & 1;

    for (int p = 1; p <= b; p++) {
        const float* Wr = W_gcn + (size_t)(start + b - p) * HH * HH + (size_t)row * HH;
        float acc[20];
#pragma unroll
        for (int c = 0; c < 20; c++) acc[c] = 0.f;
        for (int k = 0; k < HH; k++) {
            float a = Wr[k];
            const float* srcp = cur + k * CC + half * 20;
#pragma unroll
            for (int c = 0; c < 20; c++) acc[c] += a * srcp[c];
        }
        float* dstp = nxt + row * CC + half * 20;
#pragma unroll
        for (int c = 0; c < 20; c++) dstp[c] = acc[c];
        __syncthreads();

        if (p < b && t < CC) {
            const float* bb = b_gcn + (size_t)(start + b - p - 1) * HH;
            float s = 0.f;
            for (int k = 0; k < HH; k++) s += bb[k] * nxt[k * CC + t];
            if (p == 1)      g_ur_p[(b - 2) * CC + t] = s;
            else if (p == 2) g_usr_p[(b - 3) * CC + t] = s;
            else             g_us2r[t] = s;
        }
        float* tmp = cur; cur = nxt; nxt = tmp;
    }

    for (int i = t; i < HH * CC; i += 256)
        g_Acat[(size_t)b * HH * CC + i] = cur[i];
}

// ---------------- partial output GEMM: C (+)= q[M,128] @ Aj[128,40] ----------
template<bool INIT>
__global__ void __launch_bounds__(256) k_pout(
    const float* __restrict__ q, const float* __restrict__ Aj,
    float* __restrict__ C, int M)
{
    __shared__ float Bsf[HH * CC];
    __shared__ float As[16][129];
    __shared__ float su_c[CC], su_r[CC], su_sr[CC], su_s2r[CC];

    const int t = threadIdx.x;
    for (int i = t; i < HH * CC; i += 256) Bsf[i] = Aj[i];
    if (INIT && t < CC) {
        su_c[t]   = g_uc[t];
        su_r[t]   = g_ur_p[t] + g_ur_p[CC + t] + g_ur_p[2 * CC + t];
        su_sr[t]  = g_usr_p[t] + g_usr_p[CC + t];
        su_s2r[t] = g_us2r[t];
    }

    const int rg = t >> 3;
    const int cg = t & 7;
    const int rowbase = blockIdx.x * 128;

    float acc[4][5];
#pragma unroll
    for (int i = 0; i < 4; i++)
#pragma unroll
        for (int j = 0; j < 5; j++) acc[i][j] = 0.f;

    for (int kc = 0; kc < HH; kc += 16) {
#pragma unroll
        for (int rep = 0; rep < 2; rep++) {
            int idx = t + rep * 256;
            int r = idx >> 2, seg = idx & 3;
            int row = rowbase + r;
            float4 av = make_float4(0.f, 0.f, 0.f, 0.f);
            if (row < M) av = *(const float4*)(q + (size_t)row * 640 + kc + seg * 4);
            As[seg * 4 + 0][r] = av.x;
            As[seg * 4 + 1][r] = av.y;
            As[seg * 4 + 2][r] = av.z;
            As[seg * 4 + 3][r] = av.w;
        }
        __syncthreads();

#pragma unroll
        for (int k = 0; k < 16; k++) {
            float a0 = As[k][rg], a1 = As[k][rg + 32], a2 = As[k][rg + 64], a3 = As[k][rg + 96];
#pragma unroll
            for (int j = 0; j < 5; j++) {
                float bv = Bsf[(kc + k) * CC + cg + 8 * j];
                acc[0][j] += a0 * bv; acc[1][j] += a1 * bv;
                acc[2][j] += a2 * bv; acc[3][j] += a3 * bv;
            }
        }
        __syncthreads();
    }

#pragma unroll
    for (int i = 0; i < 4; i++) {
        int row = rowbase + rg + 32 * i;
        if (row < M) {
            if (INIT) {
                float rv = g_r[row], srv = g_sr[row], s2rv = g_s2r[row];
#pragma unroll
                for (int j = 0; j < 5; j++) {
                    int col = cg + 8 * j;
                    C[(size_t)row * CC + col] = acc[i][j] + su_c[col]
                        + rv * su_r[col] + srv * su_sr[col] + s2rv * su_s2r[col];
                }
            } else {
#pragma unroll
                for (int j = 0; j < 5; j++) {
                    int col = cg + 8 * j;
                    C[(size_t)row * CC + col] += acc[i][j];
                }
            }
        }
    }
}

// ---------------- stream/event setup at static-init (outside checkpoints) ----
struct StreamInit {
    bool ok = false;
    int dev = -1;
    cudaStream_t sB{}, sC{};
    cudaEvent_t ev[10]{};
    StreamInit() {
        ok = (cudaStreamCreateWithFlags(&sB, cudaStreamNonBlocking) == cudaSuccess) &&
             (cudaStreamCreateWithFlags(&sC, cudaStreamNonBlocking) == cudaSuccess);
        for (int i = 0; i < 10 && ok; i++)
            ok = (cudaEventCreateWithFlags(&ev[i], cudaEventDisableTiming) == cudaSuccess);
        if (ok) cudaGetDevice(&dev);
    }
};
static StreamInit g_si;

// ---------------- host driver ------------------------------------------------

extern "C" void kernel_launch(void* const* d_in, const int* in_sizes, int n_in,
                              void* d_out, int out_size)
{
    (void)in_sizes; (void)n_in; (void)out_size;

    const float* x     = (const float*)d_in[0];
    const int*   ei    = (const int*)d_in[1];
    const float* ew    = (const float*)d_in[2];
    const float* W_in  = (const float*)d_in[3];
    const float* b_in  = (const float*)d_in[4];
    const float* W_gcn = (const float*)d_in[5];
    const float* b_gcn = (const float*)d_in[6];
    const float* W_out = (const float*)d_in[7];
    const float* b_out = (const float*)d_in[8];
    float* outp = (float*)d_out;

    const int* src = ei;
    const int* dst = ei + EE;

    float *p_cc, *p_r, *p_sr, *p_s2r, *p_acat;
    __half *p_h16a, *p_h16b;
    cudaGetSymbolAddress((void**)&p_cc,   g_cc);
    cudaGetSymbolAddress((void**)&p_r,    g_r);
    cudaGetSymbolAddress((void**)&p_sr,   g_sr);
    cudaGetSymbolAddress((void**)&p_s2r,  g_s2r);
    cudaGetSymbolAddress((void**)&p_acat, g_Acat);
    cudaGetSymbolAddress((void**)&p_h16a, g_h16a);
    cudaGetSymbolAddress((void**)&p_h16b, g_h16b);

    int curdev = -1;
    cudaGetDevice(&curdev);
    const bool par = g_si.ok && (curdev == g_si.dev);
    cudaStream_t s0 = 0;
    cudaStream_t sB = par ? g_si.sB : (cudaStream_t)0;
    cudaStream_t sC = par ? g_si.sC : (cudaStream_t)0;
    cudaEvent_t e0   = g_si.ev[0], eB = g_si.ev[1], eC = g_si.ev[2], eR = g_si.ev[3];
    cudaEvent_t eA0  = g_si.ev[4], eA1 = g_si.ev[5], eA2 = g_si.ev[6], eA3 = g_si.ev[7];
    cudaEvent_t eF   = g_si.ev[8];

    // fork
    if (par) {
        cudaEventRecord(e0, s0);
        cudaStreamWaitEvent(sB, e0, 0);
        cudaStreamWaitEvent(sC, e0, 0);
    }

    // sB: input linear h = x @ W_in + b_in -> cc block 0 (+ fp16 mirror), HMMA
    const int GT = (NN + 127) / 128;
    gemm_mma_in<<<GT, 256, 0, sB>>>(x, W_in, b_in, p_cc, p_h16a);
    if (par) cudaEventRecord(eB, sB);

    // sC: weight chains (Acat + bias folds)
    k_chains<<<5, 256, 0, sC>>>(W_gcn, b_gcn, W_out, b_out);
    if (par) cudaEventRecord(eC, sC);

    // s0: CSR build
    k_init<<<(NN + 255) / 256, 256, 0, s0>>>();
    k_deg<<<(EE + 255) / 256, 256, 0, s0>>>(dst, ew);
    k_scan1<<<SCAN_NB, SCAN_BS, 0, s0>>>();
    k_scan2<<<1, 128, 0, s0>>>();
    k_scan3<<<SCAN_NB, SCAN_BS, 0, s0>>>();
    k_dinv_self<<<(NN + 255) / 256, 256, 0, s0>>>();
    k_fill<<<(EE + 255) / 256, 256, 0, s0>>>(src, dst, ew);

    // s0: r chain
    const int VEC_GRID = (NN * 32 + 255) / 256;
    k_spmv_vec<<<VEC_GRID, 256, 0, s0>>>(nullptr, p_r);
    k_spmv_vec<<<VEC_GRID, 256, 0, s0>>>(p_r, p_sr);
    k_spmv_vec<<<VEC_GRID, 256, 0, s0>>>(p_sr, p_s2r);
    if (par) cudaEventRecord(eR, s0);

    // s0: fp16 aggregation chain (needs h16 from sB)
    if (par) cudaStreamWaitEvent(s0, eB, 0);
    agg16<<<VEC_GRID, 256, 0, s0>>>(p_h16a, p_cc + 1 * HH, p_h16b);
    if (par) cudaEventRecord(eA0, s0);
    agg16<<<VEC_GRID, 256, 0, s0>>>(p_h16b, p_cc + 2 * HH, p_h16a);
    if (par) cudaEventRecord(eA1, s0);
    agg16<<<VEC_GRID, 256, 0, s0>>>(p_h16a, p_cc + 3 * HH, p_h16b);
    if (par) cudaEventRecord(eA2, s0);
    agg16<<<VEC_GRID, 256, 0, s0>>>(p_h16b, p_cc + 4 * HH, nullptr);
    if (par) cudaEventRecord(eA3, s0);

    // sB: partial output GEMMs, each as its q block becomes ready
    const int PG = (NN + 127) / 128;
    if (par) { cudaStreamWaitEvent(sB, eC, 0); cudaStreamWaitEvent(sB, eR, 0); }
    k_pout<true><<<PG, 256, 0, sB>>>(p_cc + 0 * HH, p_acat + 0 * HH * CC, outp, NN);
    if (par) cudaStreamWaitEvent(sB, eA0, 0);
    k_pout<false><<<PG, 256, 0, sB>>>(p_cc + 1 * HH, p_acat + 1 * HH * CC, outp, NN);
    if (par) cudaStreamWaitEvent(sB, eA1, 0);
    k_pout<false><<<PG, 256, 0, sB>>>(p_cc + 2 * HH, p_acat + 2 * HH * CC, outp, NN);
    if (par) cudaStreamWaitEvent(sB, eA2, 0);
    k_pout<false><<<PG, 256, 0, sB>>>(p_cc + 3 * HH, p_acat + 3 * HH * CC, outp, NN);
    if (par) cudaStreamWaitEvent(sB, eA3, 0);
    k_pout<false><<<PG, 256, 0, sB>>>(p_cc + 4 * HH, p_acat + 4 * HH * CC, outp, NN);

    // join back to capture stream
    if (par) {
        cudaEventRecord(eF, sB);
        cudaStreamWaitEvent(s0, eF, 0);
    }
}